// round 15
// baseline (speedup 1.0000x reference)
#include <cuda_runtime.h>
#include <cuda_fp16.h>
#include <math.h>
#include <stdint.h>

// Problem constants
#define NB 2
#define NC 128
#define FH 80
#define FW 80
#define HS 40            // downsampled H=W
#define NQ 1600          // HS*HS
#define NEPS 0.1152f     // 1152 * EPS
#define SCL 10.0f
#define MROWS 2048       // NC * 16 offsets

// fp16 mma GEMM configs
#define KT 32
#define G2_SMEM 49152    // 2 buffers x (16KB A + 8KB B)

// Static scratch
__device__ float  g_ds[NB*3*NC*NQ];          // downsampled [b][img][c][q] (fp32)
__device__ __align__(16) __half g_dsh[NB*3*NQ*256];  // [b][img][q][hi(128)|lo(128)]
__device__ float  g_E[NB*2*NQ];
__device__ float  g_ninv[NB*2*NQ];
__device__ float  g_smax[NB*2*NQ];
__device__ float  g_sinv[NB*2*NQ];
__device__ float  g_bufA[NB*2*NQ*NQ];        // ping
__device__ float  g_bufB[NB*2*NQ*NQ];        // pong
__device__ __align__(16) __half g_Gh[NB*2*MROWS*NQ];
__device__ __align__(16) __half g_ATh[NB*2*NQ*NQ];
__device__ __align__(16) __half g_Th[NB*2*MROWS*NQ];   // paste result (half)

// ---------------------------------------------------------------- downsample
__global__ void k_downsample(const float* __restrict__ left,
                             const float* __restrict__ right,
                             const float* __restrict__ mid) {
    int idx = blockIdx.x * blockDim.x + threadIdx.x;
    const int total = NB*3*NC*NQ;
    if (idx >= total) return;
    int q = idx % NQ;
    int t = idx / NQ;
    int c = t % NC; t /= NC;
    int img = t % 3; int b = t / 3;
    const float* src = (img == 0) ? left : (img == 1 ? right : mid);
    int qh = q / HS, qw = q % HS;
    g_ds[idx] = src[(size_t)((b*NC + c)*FH + 2*qh)*FW + 2*qw];
}

// ---------------- transpose-convert g_ds [c][q] -> g_dsh [q][hi|lo] (halves)
__global__ void k_cvt() {
    __shared__ float tile[32][33];
    int img = blockIdx.z;                    // b*3+img composite (0..5)
    int q0 = blockIdx.x * 32, c0 = blockIdx.y * 32;
    const float* __restrict__ src = g_ds + (size_t)img*NC*NQ;
    __half* __restrict__ dst = g_dsh + (size_t)img*NQ*256;
    int tx = threadIdx.x, ty = threadIdx.y;  // 32 x 8
    for (int r = ty; r < 32; r += 8)
        tile[r][tx] = src[(size_t)(c0+r)*NQ + q0 + tx];
    __syncthreads();
    for (int r = ty; r < 32; r += 8) {
        int q = q0 + r, c = c0 + tx;
        float v = tile[tx][r];
        __half hi = __float2half_rn(v);
        __half lo = __float2half_rn(v - __half2float(hi));
        dst[(size_t)q*256 + c]       = hi;
        dst[(size_t)q*256 + 128 + c] = lo;
    }
}

// ------------------------------------------------- channel sum-of-squares
__global__ void k_sumsq() {
    int idx = blockIdx.x*blockDim.x + threadIdx.x;
    const int total = NB*2*NQ;
    if (idx >= total) return;
    int q = idx % NQ; int t = idx / NQ;
    int s = t % 2; int b = t / 2;
    const float* p = g_ds + (size_t)(b*3 + s)*NC*NQ + q;
    float acc = 0.f;
    #pragma unroll 8
    for (int c = 0; c < NC; ++c) { float v = p[(size_t)c*NQ]; acc += v*v; }
    g_E[idx] = acc;
}

// -------------------------------------------------- patch norm
__global__ void k_norm() {
    int idx = blockIdx.x*blockDim.x + threadIdx.x;
    const int total = NB*2*NQ;
    if (idx >= total) return;
    int q = idx % NQ; int bs = idx / NQ;
    int qh = q/HS, qw = q%HS;
    float acc = NEPS;
    for (int di=-1; di<=1; ++di) {
        int h = qh+di; if (h < 0 || h >= HS) continue;
        for (int dj=-1; dj<=1; ++dj) {
            int w = qw+dj; if (w < 0 || w >= HS) continue;
            acc += g_E[bs*NQ + h*HS + w];
        }
    }
    g_ninv[idx] = rsqrtf(acc);
}

// ------------- shared fp16 mma helper
__device__ __forceinline__ void mma_f16(float* c, uint32_t a0, uint32_t a1,
                                        uint32_t a2, uint32_t a3,
                                        uint32_t b0, uint32_t b1) {
    asm volatile(
        "mma.sync.aligned.m16n8k16.row.col.f32.f16.f16.f32 "
        "{%0,%1,%2,%3}, {%4,%5,%6,%7}, {%8,%9}, {%0,%1,%2,%3};"
        : "+f"(c[0]), "+f"(c[1]), "+f"(c[2]), "+f"(c[3])
        : "r"(a0), "r"(a1), "r"(a2), "r"(a3), "r"(b0), "r"(b1));
}

// ------------- GEMM1 (split-fp16, 3 products = fp32-quality)
__global__ void __launch_bounds__(256) k_gemm1h() {
    __shared__ char smx[32768];   // Ahi 8K | Alo 8K | Bhi 8K | Blo 8K
    const int bs = blockIdx.z;
    const int b = bs >> 1, s = bs & 1;
    const __half* __restrict__ Aq = g_dsh + (size_t)(b*3 + s)*NQ*256;
    const __half* __restrict__ Bp = g_dsh + (size_t)(b*3 + 2)*NQ*256;
    float* __restrict__ Cout = g_bufA + (size_t)bs*NQ*NQ;
    const int m0 = blockIdx.x * 128, n0 = blockIdx.y * 128;
    const int t = threadIdx.x;
    const int lane = t & 31, wid = t >> 5;
    const int wm = wid & 1, wn = wid >> 1;

    const int prow = t >> 1, ps = t & 1;
    const int pmt = prow >> 4, prr = prow & 15;
    const int pgA = prr & 7;
    const int hwA = (prr >> 3) << 3;
    const int pnt = prow >> 3, pgB = prow & 7;
    const int rowA = (m0 + prow < NQ) ? (m0 + prow) : (NQ - 1);
    const int rowB = (n0 + prow < NQ) ? (n0 + prow) : (NQ - 1);

    char* Ahi = smx;
    char* Alo = smx + 8192;
    char* Bhi = smx + 16384;
    char* Blo = smx + 24576;

    float acc[4][4][4];
    #pragma unroll
    for (int i=0;i<4;i++)
        #pragma unroll
        for (int j=0;j<4;j++)
            #pragma unroll
            for (int k=0;k<4;k++) acc[i][j][k] = 0.f;

    for (int kt = 0; kt < 4; ++kt) {
        const int k0 = kt * KT;
        {
            const __half* abase = Aq + (size_t)rowA*256 + k0 + ps*16;
            const __half* bbase = Bp + (size_t)rowB*256 + k0 + ps*16;
            uint4 Ah0 = *(const uint4*)(abase);
            uint4 Ah1 = *(const uint4*)(abase + 8);
            uint4 Al0 = *(const uint4*)(abase + 128);
            uint4 Al1 = *(const uint4*)(abase + 136);
            uint4 Bh0 = *(const uint4*)(bbase);
            uint4 Bh1 = *(const uint4*)(bbase + 8);
            uint4 Bl0 = *(const uint4*)(bbase + 128);
            uint4 Bl1 = *(const uint4*)(bbase + 136);
            uint32_t l0[4], h0[4];
            char* aw; char* bw;
            l0[0]=Ah0.x; l0[1]=Ah0.y; l0[2]=Ah0.z; l0[3]=Ah0.w;
            h0[0]=Ah1.x; h0[1]=Ah1.y; h0[2]=Ah1.z; h0[3]=Ah1.w;
            aw = Ahi + ((ps*8 + pmt)*32 + pgA*4) * 16 + hwA;
            #pragma unroll
            for (int j = 0; j < 4; ++j)
                *(uint2*)(aw + j*16) = make_uint2(l0[j], h0[j]);
            l0[0]=Al0.x; l0[1]=Al0.y; l0[2]=Al0.z; l0[3]=Al0.w;
            h0[0]=Al1.x; h0[1]=Al1.y; h0[2]=Al1.z; h0[3]=Al1.w;
            aw = Alo + ((ps*8 + pmt)*32 + pgA*4) * 16 + hwA;
            #pragma unroll
            for (int j = 0; j < 4; ++j)
                *(uint2*)(aw + j*16) = make_uint2(l0[j], h0[j]);
            l0[0]=Bh0.x; l0[1]=Bh0.y; l0[2]=Bh0.z; l0[3]=Bh0.w;
            h0[0]=Bh1.x; h0[1]=Bh1.y; h0[2]=Bh1.z; h0[3]=Bh1.w;
            bw = Bhi + ((ps*16 + pnt)*32 + pgB*4) * 8;
            #pragma unroll
            for (int j = 0; j < 4; ++j)
                *(uint2*)(bw + j*8) = make_uint2(l0[j], h0[j]);
            l0[0]=Bl0.x; l0[1]=Bl0.y; l0[2]=Bl0.z; l0[3]=Bl0.w;
            h0[0]=Bl1.x; h0[1]=Bl1.y; h0[2]=Bl1.z; h0[3]=Bl1.w;
            bw = Blo + ((ps*16 + pnt)*32 + pgB*4) * 8;
            #pragma unroll
            for (int j = 0; j < 4; ++j)
                *(uint2*)(bw + j*8) = make_uint2(l0[j], h0[j]);
        }
        __syncthreads();

        #pragma unroll
        for (int ss = 0; ss < 2; ++ss) {
            uint4 afh[4], afl[4]; uint2 bfh[4], bfl[4];
            #pragma unroll
            for (int mt = 0; mt < 4; ++mt) {
                afh[mt] = *(const uint4*)(Ahi + (((ss*8 + wm*4 + mt)*32 + lane) * 16));
                afl[mt] = *(const uint4*)(Alo + (((ss*8 + wm*4 + mt)*32 + lane) * 16));
            }
            #pragma unroll
            for (int nt = 0; nt < 4; ++nt) {
                bfh[nt] = *(const uint2*)(Bhi + (((ss*16 + wn*4 + nt)*32 + lane) * 8));
                bfl[nt] = *(const uint2*)(Blo + (((ss*16 + wn*4 + nt)*32 + lane) * 8));
            }
            #pragma unroll
            for (int mt = 0; mt < 4; ++mt)
                #pragma unroll
                for (int nt = 0; nt < 4; ++nt) {
                    mma_f16(acc[mt][nt], afh[mt].x, afh[mt].z, afh[mt].y, afh[mt].w,
                            bfh[nt].x, bfh[nt].y);
                    mma_f16(acc[mt][nt], afh[mt].x, afh[mt].z, afh[mt].y, afh[mt].w,
                            bfl[nt].x, bfl[nt].y);
                    mma_f16(acc[mt][nt], afl[mt].x, afl[mt].z, afl[mt].y, afl[mt].w,
                            bfh[nt].x, bfh[nt].y);
                }
        }
        __syncthreads();
    }

    #pragma unroll
    for (int mt = 0; mt < 4; ++mt) {
        int m = m0 + wm*64 + mt*16 + (lane >> 2);
        #pragma unroll
        for (int nt = 0; nt < 4; ++nt) {
            int n = n0 + wn*32 + nt*8 + 2*(lane & 3);
            if (n < NQ) {
                if (m < NQ)
                    *(float2*)&Cout[(size_t)m*NQ + n] =
                        make_float2(acc[mt][nt][0], acc[mt][nt][1]);
                if (m + 8 < NQ)
                    *(float2*)&Cout[(size_t)(m+8)*NQ + n] =
                        make_float2(acc[mt][nt][2], acc[mt][nt][3]);
            }
        }
    }
}

// ---------- FUSED passes A+B (slab-tiled): bufA -> bufB
__global__ void __launch_bounds__(256) k_psAB() {
    __shared__ float sl[3][40][40];
    int blk = blockIdx.x;                 // bs*1600 + qh*40 + ph
    int ph = blk % HS; int t2 = blk / HS;
    int qh = t2 % HS; int bs = t2 / HS;
    const float* __restrict__ In = g_bufA + (size_t)bs*NQ*NQ;
    float* __restrict__ Out = g_bufB + (size_t)bs*NQ*NQ;
    const int tid = threadIdx.x;

    #pragma unroll
    for (int e = -1; e <= 1; ++e) {
        int Qh = qh + e, Ph = ph + e;
        if (Qh < 0 || Qh >= HS || Ph < 0 || Ph >= HS) continue;
        const float* base = In + (size_t)(Qh*HS)*NQ + Ph*HS;
        for (int i = tid; i < 400; i += 256) {
            int row = i / 10, c4 = (i % 10) * 4;
            *(float4*)&sl[e+1][row][c4] = *(const float4*)(base + (size_t)row*NQ + c4);
        }
    }
    __syncthreads();

    const float* __restrict__ ninv = g_ninv + bs*NQ;
    const bool em = (qh > 0)    && (ph > 0);
    const bool ez = true;
    const bool ep = (qh < HS-1) && (ph < HS-1);
    for (int i = tid; i < 1600; i += 256) {
        int qw = i / 40, pw = i % 40;
        bool dp = (qw < HS-1) && (pw < HS-1);
        bool dmm = (qw > 0) && (pw > 0);
        float acc = 0.f;
        #pragma unroll
        for (int eh = 0; eh < 3; ++eh) {
            bool ok = (eh == 0) ? em : ((eh == 1) ? ez : ep);
            if (!ok) continue;
            float s = sl[eh][qw][pw];
            if (dmm) s += sl[eh][qw-1][pw-1];
            if (dp)  s += sl[eh][qw+1][pw+1];
            acc += s;
        }
        Out[(size_t)(qh*HS + qw)*NQ + ph*HS + pw] = acc * ninv[qh*HS + qw];
    }
}

// ---------- pass C (fuse1, flat diag), DIAGONAL MARCHING: bufB -> bufA
__global__ void k_passC() {
    int idx = blockIdx.x*blockDim.x + threadIdx.x;
    const int NP = NQ + 4;                 // p0 in [-3, NQ]
    const int total = NB*2*(NQ/4)*NP;
    if (idx >= total) return;
    int p0 = (idx % NP) - 3;
    int t = idx / NP;
    int qg = t % (NQ/4);
    int bs = t / (NQ/4);
    int q0 = qg * 4;
    const float* __restrict__ S = g_bufB + (size_t)bs*NQ*NQ;
    float* __restrict__ O = g_bufA + (size_t)bs*NQ*NQ;
    float diag[6];
    #pragma unroll
    for (int j = 0; j < 6; ++j) {
        int r = q0 - 1 + j, c = p0 - 1 + j;
        diag[j] = (r >= 0 && r < NQ && c >= 0 && c < NQ) ? S[(size_t)r*NQ + c] : 0.f;
    }
    #pragma unroll
    for (int i = 0; i < 4; ++i) {
        int q = q0 + i, p = p0 + i;
        if (p < 0 || p >= NQ) continue;
        float acc = diag[i+1];
        if (q > 0 && p > 0)       acc += diag[i];
        if (q < NQ-1 && p < NQ-1) acc += diag[i+2];
        O[(size_t)q*NQ + p] = acc;
    }
}

// ---------- pass D (fuse2), DIAGONAL MARCHING in (qh,ph): bufA -> bufB
__global__ void k_passD() {
    int idx = blockIdx.x*blockDim.x + threadIdx.x;
    const int NPH = HS + 3;                // ph0 in [-3, 39] -> 43 values
    const int total = NB*2*10*HS*NPH*HS;   // 2,752,000
    if (idx >= total) return;
    int pw = idx % HS; int t = idx / HS;
    int ph0 = (t % NPH) - 3; t /= NPH;
    int qw = t % HS; t /= HS;
    int qhg = t % 10; int bs = t / 10;
    const float* __restrict__ F = g_bufA + (size_t)bs*NQ*NQ;
    float* __restrict__ O = g_bufB + (size_t)bs*NQ*NQ;
    const int qh0 = qhg*4;
    if (qhg >= 1 && qhg <= 8 && ph0 >= 1 && ph0 <= 34) {
        float diag[6];
        #pragma unroll
        for (int j = 0; j < 6; ++j)
            diag[j] = F[(size_t)((qh0-1+j)*HS + qw)*NQ + (ph0-1+j)*HS + pw];
        #pragma unroll
        for (int i = 0; i < 4; ++i)
            O[(size_t)((qh0+i)*HS + qw)*NQ + (ph0+i)*HS + pw] =
                diag[i] + diag[i+1] + diag[i+2];
    } else {
        #pragma unroll
        for (int i = 0; i < 4; ++i) {
            int qh = qh0 + i, ph = ph0 + i;
            if (ph < 0 || ph >= HS) continue;
            int q = qh*HS + qw, p = ph*HS + pw;
            float acc = F[(size_t)q*NQ + p];
            if (q > 0 && p > 0) {
                int qm = (qh > 0) ? (q - HS) : ((HS-1)*HS + qw - 1);
                int pm = (ph > 0) ? (p - HS) : ((HS-1)*HS + pw - 1);
                acc += F[(size_t)qm*NQ + pm];
            }
            if (q < NQ-1 && p < NQ-1) {
                int qp = (qh < HS-1) ? (q + HS) : (qw + 1);
                int pp = (ph < HS-1) ? (p + HS) : (pw + 1);
                acc += F[(size_t)qp*NQ + pp];
            }
            O[(size_t)q*NQ + p] = acc;
        }
    }
}

// --------------- softmax stats, online, 4 independent ILP chains (reads bufB)
__global__ void k_softmax_stats() {
    int bs = blockIdx.y;
    int p0 = blockIdx.x * 64;
    const float* __restrict__ F = g_bufB + (size_t)bs*NQ*NQ;
    int px = threadIdx.x & 63;
    int qy = threadIdx.x >> 6;        // 0..3
    int p = p0 + px;
    __shared__ float redm[4][64], reds[4][64];
    float mx[4] = {-3.4e38f, -3.4e38f, -3.4e38f, -3.4e38f};
    float sm[4] = {0.f, 0.f, 0.f, 0.f};
    // 1600/16 = 100 iterations, 4 independent online chains per thread
    for (int q = qy; q < NQ; q += 16) {
        #pragma unroll
        for (int j = 0; j < 4; ++j) {
            float v = F[(size_t)(q + 4*j)*NQ + p];
            if (v <= mx[j]) {
                sm[j] += __expf(SCL * (v - mx[j]));
            } else {
                sm[j] = sm[j] * __expf(SCL * (mx[j] - v)) + 1.f;
                mx[j] = v;
            }
        }
    }
    // merge 4 chains
    float M4 = fmaxf(fmaxf(mx[0], mx[1]), fmaxf(mx[2], mx[3]));
    float S4 = sm[0] * __expf(SCL * (mx[0] - M4))
             + sm[1] * __expf(SCL * (mx[1] - M4))
             + sm[2] * __expf(SCL * (mx[2] - M4))
             + sm[3] * __expf(SCL * (mx[3] - M4));
    redm[qy][px] = M4;
    reds[qy][px] = S4;
    __syncthreads();
    if (qy == 0) {
        float m0_ = redm[0][px], m1 = redm[1][px], m2 = redm[2][px], m3 = redm[3][px];
        float M = fmaxf(fmaxf(m0_, m1), fmaxf(m2, m3));
        float S = reds[0][px] * __expf(SCL * (m0_ - M))
                + reds[1][px] * __expf(SCL * (m1 - M))
                + reds[2][px] * __expf(SCL * (m2 - M))
                + reds[3][px] * __expf(SCL * (m3 - M));
        g_smax[bs*NQ + p] = M;
        g_sinv[bs*NQ + p] = 1.0f / S;
    }
}

// --------------- attnT: transposed, normalized attn as half (bufB -> g_ATh)
__global__ void k_attnT() {
    __shared__ float tile[32][33];
    int bs = blockIdx.z;
    int q0 = blockIdx.x * 32, p0 = blockIdx.y * 32;
    const float* __restrict__ F = g_bufB + (size_t)bs*NQ*NQ;
    __half* __restrict__ O = g_ATh + (size_t)bs*NQ*NQ;
    int tx = threadIdx.x, ty = threadIdx.y;  // 32 x 8
    for (int r = ty; r < 32; r += 8)
        tile[r][tx] = F[(size_t)(q0+r)*NQ + p0 + tx];
    __syncthreads();
    for (int r = ty; r < 32; r += 8) {
        int p = p0 + r;
        float e = __expf(SCL * (tile[tx][r] - g_smax[bs*NQ + p])) * g_sinv[bs*NQ + p];
        O[(size_t)p*NQ + q0 + tx] = __float2half_rn(e);
    }
}

// --------------- build paste operand G[bs][m][q] as half, 8 q per thread
__global__ void k_buildG(const float* __restrict__ raw_left,
                         const float* __restrict__ raw_right) {
    int idx = blockIdx.x*blockDim.x + threadIdx.x;
    const int total8 = NB*2*MROWS*(NQ/8);
    if (idx >= total8) return;
    int q8 = (idx % (NQ/8)) * 8;
    int t = idx / (NQ/8);
    int m = t % MROWS;
    int bs = t / MROWS;
    int b = bs >> 1, s = bs & 1;
    int c = m >> 4;
    int o = m & 15;
    int dy = (o >> 2) - 1, dx = (o & 3) - 1;
    int qh = q8 / HS, qw0 = q8 - (q8/HS)*HS;
    int y = 2*qh + dy;
    const float* raw = (s ? raw_right : raw_left) + (size_t)(b*NC + c)*FH*FW;
    __half hv[8];
    if (y >= 0 && y < FH) {
        const float* rrow = raw + (size_t)y*FW;
        #pragma unroll
        for (int j = 0; j < 8; ++j) {
            int x = 2*(qw0 + j) + dx;
            hv[j] = (x >= 0 && x < FW) ? __float2half_rn(rrow[x]) : __half(0.f);
        }
    } else {
        #pragma unroll
        for (int j = 0; j < 8; ++j) hv[j] = __half(0.f);
    }
    *(uint4*)&g_Gh[(size_t)(bs*MROWS + m)*NQ + q8] = *(uint4*)hv;
}

// ------------- GEMM2 (mma.sync fp16, f32 accum): T[m,p] = sum_q G[m,q] * attnT[p,q]
// CTA tile 256(m) x 128(n), 512 threads (16 warps: 4m x 4n), warp tile 64x32.
// Output written as fp16 (halves epilogue + combine traffic).
__global__ void __launch_bounds__(512) k_gemm2h() {
    extern __shared__ char smx[];
    const int bs = blockIdx.z;
    const __half* __restrict__ Gm = g_Gh  + (size_t)bs*MROWS*NQ;
    const __half* __restrict__ Bm = g_ATh + (size_t)bs*NQ*NQ;
    __half* __restrict__ Tm = g_Th + (size_t)bs*MROWS*NQ;
    const int m0 = blockIdx.x * 256, n0 = blockIdx.y * 128;
    const int t = threadIdx.x;
    const int lane = t & 31, wid = t >> 5;
    const int wm = wid & 3, wn = wid >> 2;      // warp grid 4(m) x 4(n)

    const int aRow = t >> 1, psA = t & 1;
    const int aMg = aRow >> 4, aRr = aRow & 15;
    const int aPg = aRr & 7;
    const int aHw = (aRr >> 3) << 3;
    const bool hasB = (t < 256);
    const int bRow = t >> 1;
    const int psB = t & 1;
    const int bNg = bRow >> 3, bPg = bRow & 7;
    const bool pBvalid = hasB && ((n0 + bRow) < NQ);

    uint32_t al[4], ah[4], bl[4], bh[4];

    float acc[4][4][4];
    #pragma unroll
    for (int i=0;i<4;i++)
        #pragma unroll
        for (int j=0;j<4;j++)
            #pragma unroll
            for (int k=0;k<4;k++) acc[i][j][k] = 0.f;

    {
        const uint4* pa = (const uint4*)(Gm + (size_t)(m0+aRow)*NQ + psA*16);
        uint4 lo = pa[0], hi = pa[1];
        al[0]=lo.x; al[1]=lo.y; al[2]=lo.z; al[3]=lo.w;
        ah[0]=hi.x; ah[1]=hi.y; ah[2]=hi.z; ah[3]=hi.w;
        if (pBvalid) {
            const uint4* pb = (const uint4*)(Bm + (size_t)(n0+bRow)*NQ + psB*16);
            uint4 blo = pb[0], bhi = pb[1];
            bl[0]=blo.x; bl[1]=blo.y; bl[2]=blo.z; bl[3]=blo.w;
            bh[0]=bhi.x; bh[1]=bhi.y; bh[2]=bhi.z; bh[3]=bhi.w;
        } else {
            #pragma unroll
            for (int j=0;j<4;j++) { bl[j]=0u; bh[j]=0u; }
        }
    }

    const int NTILES = NQ / KT;
    for (int it = 0; it < NTILES; ++it) {
        char* base = smx + (it & 1) * 24576;
        char* Asl = base;
        char* Bsl = base + 16384;

        {
            char* aw = Asl + ((psA*16 + aMg)*32 + aPg*4) * 16 + aHw;
            #pragma unroll
            for (int j = 0; j < 4; ++j)
                *(uint2*)(aw + j*16) = make_uint2(al[j], ah[j]);
            if (hasB) {
                char* bw = Bsl + ((psB*16 + bNg)*32 + bPg*4) * 8;
                #pragma unroll
                for (int j = 0; j < 4; ++j)
                    *(uint2*)(bw + j*8)  = make_uint2(bl[j], bh[j]);
            }
        }
        __syncthreads();

        if (it + 1 < NTILES) {
            int k0n = (it + 1) * KT;
            const uint4* pa = (const uint4*)(Gm + (size_t)(m0+aRow)*NQ + k0n + psA*16);
            uint4 lo = pa[0], hi = pa[1];
            al[0]=lo.x; al[1]=lo.y; al[2]=lo.z; al[3]=lo.w;
            ah[0]=hi.x; ah[1]=hi.y; ah[2]=hi.z; ah[3]=hi.w;
            if (pBvalid) {
                const uint4* pb = (const uint4*)(Bm + (size_t)(n0+bRow)*NQ + k0n + psB*16);
                uint4 blo = pb[0], bhi = pb[1];
                bl[0]=blo.x; bl[1]=blo.y; bl[2]=blo.z; bl[3]=blo.w;
                bh[0]=bhi.x; bh[1]=bhi.y; bh[2]=bhi.z; bh[3]=bhi.w;
            }
        }

        #pragma unroll
        for (int s = 0; s < 2; ++s) {
            uint4 af[4]; uint2 bf[4];
            #pragma unroll
            for (int mt = 0; mt < 4; ++mt)
                af[mt] = *(const uint4*)(Asl + (((s*16 + wm*4 + mt)*32 + lane) * 16));
            #pragma unroll
            for (int nt = 0; nt < 4; ++nt)
                bf[nt] = *(const uint2*)(Bsl + (((s*16 + wn*4 + nt)*32 + lane) * 8));
            #pragma unroll
            for (int mt = 0; mt < 4; ++mt)
                #pragma unroll
                for (int nt = 0; nt < 4; ++nt)
                    mma_f16(acc[mt][nt], af[mt].x, af[mt].z, af[mt].y, af[mt].w,
                            bf[nt].x, bf[nt].y);
        }
    }

    #pragma unroll
    for (int mt = 0; mt < 4; ++mt) {
        int m = m0 + wm*64 + mt*16 + (lane >> 2);
        #pragma unroll
        for (int nt = 0; nt < 4; ++nt) {
            int n = n0 + wn*32 + nt*8 + 2*(lane & 3);
            if (n < NQ) {
                *(__half2*)&Tm[(size_t)m*NQ + n] =
                    __floats2half2_rn(acc[mt][nt][0], acc[mt][nt][1]);
                *(__half2*)&Tm[(size_t)(m+8)*NQ + n] =
                    __floats2half2_rn(acc[mt][nt][2], acc[mt][nt][3]);
            }
        }
    }
}

// ------------- gather epilogue + cosine-window blend -> output (2,128,80,80)
__global__ void k_combine(float* __restrict__ out) {
    int idx = blockIdx.x*blockDim.x + threadIdx.x;
    const int total = NB*NC*FH*FW;
    if (idx >= total) return;
    int X = idx % FW; int t = idx / FW;
    int Y = t % FH; t /= FH;
    int c = t % NC; int b = t / NC;

    int dys[2], hh[2]; int ny = 0;
    if ((Y & 1) == 0) {
        dys[ny] = 0; hh[ny] = Y >> 1; ny++;
        if (Y >= 2) { dys[ny] = 2; hh[ny] = (Y-2) >> 1; ny++; }
    } else {
        dys[ny] = 1; hh[ny] = (Y-1) >> 1; ny++;
        if (Y <= 2*HS - 3) { dys[ny] = -1; hh[ny] = (Y+1) >> 1; ny++; }
    }
    int dxs[2], ww[2]; int nx = 0;
    if ((X & 1) == 0) {
        dxs[nx] = 0; ww[nx] = X >> 1; nx++;
        if (X >= 2) { dxs[nx] = 2; ww[nx] = (X-2) >> 1; nx++; }
    } else {
        dxs[nx] = 1; ww[nx] = (X-1) >> 1; nx++;
        if (X <= 2*HS - 3) { dxs[nx] = -1; ww[nx] = (X+1) >> 1; nx++; }
    }

    const float PI = 3.14159265358979323846f;
    float wl = 0.5f*(1.f + cosf(PI * (float)X        / (float)(FW-1)));
    float wr = 0.5f*(1.f + cosf(PI * (float)(FW-1-X) / (float)(FW-1)));

    float res = 0.f;
    for (int s = 0; s < 2; ++s) {
        const __half* T = g_Th + (size_t)(b*2 + s)*MROWS*NQ;
        float acc = 0.f;
        for (int iy = 0; iy < ny; ++iy) {
            for (int ix = 0; ix < nx; ++ix) {
                int m = c*16 + (dys[iy]+1)*4 + (dxs[ix]+1);
                acc += __half2float(T[(size_t)m*NQ + hh[iy]*HS + ww[ix]]);
            }
        }
        res += (s == 0 ? wl : wr) * 0.25f * acc;
    }
    out[idx] = res;
}

// ------------------------------------------------------------------ launcher
extern "C" void kernel_launch(void* const* d_in, const int* in_sizes, int n_in,
                              void* d_out, int out_size) {
    const float* left      = (const float*)d_in[0];
    const float* right     = (const float*)d_in[1];
    const float* mid       = (const float*)d_in[2];
    const float* raw_left  = (const float*)d_in[3];
    const float* raw_right = (const float*)d_in[4];
    float* outp = (float*)d_out;

    cudaFuncSetAttribute(k_gemm2h, cudaFuncAttributeMaxDynamicSharedMemorySize, G2_SMEM);

    int t1 = NB*3*NC*NQ;
    k_downsample<<<(t1+255)/256, 256>>>(left, right, mid);
    k_cvt<<<dim3(NQ/32, NC/32, NB*3), dim3(32, 8)>>>();
    int t2 = NB*2*NQ;
    k_sumsq<<<(t2+127)/128, 128>>>();
    k_norm<<<(t2+127)/128, 128>>>();

    dim3 g1((NQ+127)/128, (NQ+127)/128, NB*2);   // 13 x 13 x 4
    k_gemm1h<<<g1, 256>>>();

    k_psAB<<<NB*2*HS*HS, 256>>>();               // fused passes A+B

    int tC = NB*2*(NQ/4)*(NQ+4);
    k_passC<<<(tC+255)/256, 256>>>();

    int tD = NB*2*10*HS*(HS+3)*HS;
    k_passD<<<(tD+255)/256, 256>>>();

    k_softmax_stats<<<dim3(NQ/64, NB*2), 256>>>();
    k_attnT<<<dim3(NQ/32, NQ/32, NB*2), dim3(32, 8)>>>();

    int tg8 = NB*2*MROWS*(NQ/8);
    k_buildG<<<(tg8+255)/256, 256>>>(raw_left, raw_right);

    dim3 g2(MROWS/256, (NQ+127)/128, NB*2);      // 8 x 13 x 4
    k_gemm2h<<<g2, 512, G2_SMEM>>>();

    int to = NB*NC*FH*FW;
    k_combine<<<(to+255)/256, 256>>>(outp);
}

// round 16
// speedup vs baseline: 1.0456x; 1.0456x over previous
#include <cuda_runtime.h>
#include <cuda_fp16.h>
#include <math.h>
#include <stdint.h>

// Problem constants
#define NB 2
#define NC 128
#define FH 80
#define FW 80
#define HS 40            // downsampled H=W
#define NQ 1600          // HS*HS
#define NEPS 0.1152f     // 1152 * EPS
#define SCL 10.0f
#define MROWS 2048       // NC * 16 offsets

// fp16 mma GEMM configs
#define KT 32
#define G2_SMEM 49152    // 2 buffers x (16KB A + 8KB B)

// Static scratch
__device__ __align__(16) __half g_dsh[NB*3*NQ*256];  // [b][img][q][hi(128)|lo(128)]
__device__ float  g_E[NB*2*NQ];
__device__ float  g_ninv[NB*2*NQ];
__device__ float  g_smax[NB*2*NQ];
__device__ float  g_sinv[NB*2*NQ];
__device__ float  g_bufA[NB*2*NQ*NQ];        // ping
__device__ float  g_bufB[NB*2*NQ*NQ];        // pong
__device__ __align__(16) __half g_Gh[NB*2*MROWS*NQ];
__device__ __align__(16) __half g_ATh[NB*2*NQ*NQ];
__device__ float  g_T[NB*2*MROWS*NQ];        // paste result (fp32)

// ---------------- downsample + transpose + split-fp16 convert, direct from inputs
// writes g_dsh[img][q][hi(0..127) | lo(128..255)]
__global__ void k_cvt(const float* __restrict__ left,
                      const float* __restrict__ right,
                      const float* __restrict__ mid) {
    __shared__ float tile[32][33];
    int img = blockIdx.z;                    // b*3 + which
    int b = img / 3, which = img % 3;
    int q0 = blockIdx.x * 32, c0 = blockIdx.y * 32;
    const float* __restrict__ src =
        ((which == 0) ? left : (which == 1 ? right : mid)) + (size_t)(b*NC)*FH*FW;
    __half* __restrict__ dst = g_dsh + (size_t)img*NQ*256;
    int tx = threadIdx.x, ty = threadIdx.y;  // 32 x 8
    // load: tile[r][tx] = x[c0+r, q0+tx]  (strided-by-2 gather from full-res image)
    for (int r = ty; r < 32; r += 8) {
        int q = q0 + tx;
        int qh = q / HS, qw = q - qh*HS;
        tile[r][tx] = src[(size_t)(c0+r)*FH*FW + (2*qh)*FW + 2*qw];
    }
    __syncthreads();
    for (int r = ty; r < 32; r += 8) {
        int q = q0 + r, c = c0 + tx;
        float v = tile[tx][r];
        __half hi = __float2half_rn(v);
        __half lo = __float2half_rn(v - __half2float(hi));
        dst[(size_t)q*256 + c]       = hi;
        dst[(size_t)q*256 + 128 + c] = lo;
    }
}

// ------------------------------------------------- channel sum-of-squares (from g_dsh)
__global__ void k_sumsq() {
    int idx = blockIdx.x*blockDim.x + threadIdx.x;
    const int total = NB*2*NQ;
    if (idx >= total) return;
    int q = idx % NQ; int t = idx / NQ;
    int s = t % 2; int b = t / 2;
    const __half* row = g_dsh + (size_t)(b*3 + s)*NQ*256 + (size_t)q*256;
    float acc = 0.f;
    #pragma unroll 16
    for (int c = 0; c < 128; c += 2) {
        __half2 h = *(const __half2*)(row + c);
        __half2 l = *(const __half2*)(row + 128 + c);
        float v0 = __half2float(__low2half(h))  + __half2float(__low2half(l));
        float v1 = __half2float(__high2half(h)) + __half2float(__high2half(l));
        acc += v0*v0 + v1*v1;
    }
    g_E[idx] = acc;
}

// -------------------------------------------------- patch norm
__global__ void k_norm() {
    int idx = blockIdx.x*blockDim.x + threadIdx.x;
    const int total = NB*2*NQ;
    if (idx >= total) return;
    int q = idx % NQ; int bs = idx / NQ;
    int qh = q/HS, qw = q%HS;
    float acc = NEPS;
    for (int di=-1; di<=1; ++di) {
        int h = qh+di; if (h < 0 || h >= HS) continue;
        for (int dj=-1; dj<=1; ++dj) {
            int w = qw+dj; if (w < 0 || w >= HS) continue;
            acc += g_E[bs*NQ + h*HS + w];
        }
    }
    g_ninv[idx] = rsqrtf(acc);
}

// ------------- shared fp16 mma helper
__device__ __forceinline__ void mma_f16(float* c, uint32_t a0, uint32_t a1,
                                        uint32_t a2, uint32_t a3,
                                        uint32_t b0, uint32_t b1) {
    asm volatile(
        "mma.sync.aligned.m16n8k16.row.col.f32.f16.f16.f32 "
        "{%0,%1,%2,%3}, {%4,%5,%6,%7}, {%8,%9}, {%0,%1,%2,%3};"
        : "+f"(c[0]), "+f"(c[1]), "+f"(c[2]), "+f"(c[3])
        : "r"(a0), "r"(a1), "r"(a2), "r"(a3), "r"(b0), "r"(b1));
}

// ------------- GEMM1 (split-fp16, 3 products = fp32-quality)
__global__ void __launch_bounds__(256) k_gemm1h() {
    __shared__ char smx[32768];   // Ahi 8K | Alo 8K | Bhi 8K | Blo 8K
    const int bs = blockIdx.z;
    const int b = bs >> 1, s = bs & 1;
    const __half* __restrict__ Aq = g_dsh + (size_t)(b*3 + s)*NQ*256;
    const __half* __restrict__ Bp = g_dsh + (size_t)(b*3 + 2)*NQ*256;
    float* __restrict__ Cout = g_bufA + (size_t)bs*NQ*NQ;
    const int m0 = blockIdx.x * 128, n0 = blockIdx.y * 128;
    const int t = threadIdx.x;
    const int lane = t & 31, wid = t >> 5;
    const int wm = wid & 1, wn = wid >> 1;

    const int prow = t >> 1, ps = t & 1;
    const int pmt = prow >> 4, prr = prow & 15;
    const int pgA = prr & 7;
    const int hwA = (prr >> 3) << 3;
    const int pnt = prow >> 3, pgB = prow & 7;
    const int rowA = (m0 + prow < NQ) ? (m0 + prow) : (NQ - 1);
    const int rowB = (n0 + prow < NQ) ? (n0 + prow) : (NQ - 1);

    char* Ahi = smx;
    char* Alo = smx + 8192;
    char* Bhi = smx + 16384;
    char* Blo = smx + 24576;

    float acc[4][4][4];
    #pragma unroll
    for (int i=0;i<4;i++)
        #pragma unroll
        for (int j=0;j<4;j++)
            #pragma unroll
            for (int k=0;k<4;k++) acc[i][j][k] = 0.f;

    for (int kt = 0; kt < 4; ++kt) {
        const int k0 = kt * KT;
        {
            const __half* abase = Aq + (size_t)rowA*256 + k0 + ps*16;
            const __half* bbase = Bp + (size_t)rowB*256 + k0 + ps*16;
            uint4 Ah0 = *(const uint4*)(abase);
            uint4 Ah1 = *(const uint4*)(abase + 8);
            uint4 Al0 = *(const uint4*)(abase + 128);
            uint4 Al1 = *(const uint4*)(abase + 136);
            uint4 Bh0 = *(const uint4*)(bbase);
            uint4 Bh1 = *(const uint4*)(bbase + 8);
            uint4 Bl0 = *(const uint4*)(bbase + 128);
            uint4 Bl1 = *(const uint4*)(bbase + 136);
            uint32_t l0[4], h0[4];
            char* aw; char* bw;
            l0[0]=Ah0.x; l0[1]=Ah0.y; l0[2]=Ah0.z; l0[3]=Ah0.w;
            h0[0]=Ah1.x; h0[1]=Ah1.y; h0[2]=Ah1.z; h0[3]=Ah1.w;
            aw = Ahi + ((ps*8 + pmt)*32 + pgA*4) * 16 + hwA;
            #pragma unroll
            for (int j = 0; j < 4; ++j)
                *(uint2*)(aw + j*16) = make_uint2(l0[j], h0[j]);
            l0[0]=Al0.x; l0[1]=Al0.y; l0[2]=Al0.z; l0[3]=Al0.w;
            h0[0]=Al1.x; h0[1]=Al1.y; h0[2]=Al1.z; h0[3]=Al1.w;
            aw = Alo + ((ps*8 + pmt)*32 + pgA*4) * 16 + hwA;
            #pragma unroll
            for (int j = 0; j < 4; ++j)
                *(uint2*)(aw + j*16) = make_uint2(l0[j], h0[j]);
            l0[0]=Bh0.x; l0[1]=Bh0.y; l0[2]=Bh0.z; l0[3]=Bh0.w;
            h0[0]=Bh1.x; h0[1]=Bh1.y; h0[2]=Bh1.z; h0[3]=Bh1.w;
            bw = Bhi + ((ps*16 + pnt)*32 + pgB*4) * 8;
            #pragma unroll
            for (int j = 0; j < 4; ++j)
                *(uint2*)(bw + j*8) = make_uint2(l0[j], h0[j]);
            l0[0]=Bl0.x; l0[1]=Bl0.y; l0[2]=Bl0.z; l0[3]=Bl0.w;
            h0[0]=Bl1.x; h0[1]=Bl1.y; h0[2]=Bl1.z; h0[3]=Bl1.w;
            bw = Blo + ((ps*16 + pnt)*32 + pgB*4) * 8;
            #pragma unroll
            for (int j = 0; j < 4; ++j)
                *(uint2*)(bw + j*8) = make_uint2(l0[j], h0[j]);
        }
        __syncthreads();

        #pragma unroll
        for (int ss = 0; ss < 2; ++ss) {
            uint4 afh[4], afl[4]; uint2 bfh[4], bfl[4];
            #pragma unroll
            for (int mt = 0; mt < 4; ++mt) {
                afh[mt] = *(const uint4*)(Ahi + (((ss*8 + wm*4 + mt)*32 + lane) * 16));
                afl[mt] = *(const uint4*)(Alo + (((ss*8 + wm*4 + mt)*32 + lane) * 16));
            }
            #pragma unroll
            for (int nt = 0; nt < 4; ++nt) {
                bfh[nt] = *(const uint2*)(Bhi + (((ss*16 + wn*4 + nt)*32 + lane) * 8));
                bfl[nt] = *(const uint2*)(Blo + (((ss*16 + wn*4 + nt)*32 + lane) * 8));
            }
            #pragma unroll
            for (int mt = 0; mt < 4; ++mt)
                #pragma unroll
                for (int nt = 0; nt < 4; ++nt) {
                    mma_f16(acc[mt][nt], afh[mt].x, afh[mt].z, afh[mt].y, afh[mt].w,
                            bfh[nt].x, bfh[nt].y);
                    mma_f16(acc[mt][nt], afh[mt].x, afh[mt].z, afh[mt].y, afh[mt].w,
                            bfl[nt].x, bfl[nt].y);
                    mma_f16(acc[mt][nt], afl[mt].x, afl[mt].z, afl[mt].y, afl[mt].w,
                            bfh[nt].x, bfh[nt].y);
                }
        }
        __syncthreads();
    }

    #pragma unroll
    for (int mt = 0; mt < 4; ++mt) {
        int m = m0 + wm*64 + mt*16 + (lane >> 2);
        #pragma unroll
        for (int nt = 0; nt < 4; ++nt) {
            int n = n0 + wn*32 + nt*8 + 2*(lane & 3);
            if (n < NQ) {
                if (m < NQ)
                    *(float2*)&Cout[(size_t)m*NQ + n] =
                        make_float2(acc[mt][nt][0], acc[mt][nt][1]);
                if (m + 8 < NQ)
                    *(float2*)&Cout[(size_t)(m+8)*NQ + n] =
                        make_float2(acc[mt][nt][2], acc[mt][nt][3]);
            }
        }
    }
}

// ---------- FUSED passes A+B (slab-tiled): bufA -> bufB
__global__ void __launch_bounds__(256) k_psAB() {
    __shared__ float sl[3][40][40];
    int blk = blockIdx.x;                 // bs*1600 + qh*40 + ph
    int ph = blk % HS; int t2 = blk / HS;
    int qh = t2 % HS; int bs = t2 / HS;
    const float* __restrict__ In = g_bufA + (size_t)bs*NQ*NQ;
    float* __restrict__ Out = g_bufB + (size_t)bs*NQ*NQ;
    const int tid = threadIdx.x;

    #pragma unroll
    for (int e = -1; e <= 1; ++e) {
        int Qh = qh + e, Ph = ph + e;
        if (Qh < 0 || Qh >= HS || Ph < 0 || Ph >= HS) continue;
        const float* base = In + (size_t)(Qh*HS)*NQ + Ph*HS;
        for (int i = tid; i < 400; i += 256) {
            int row = i / 10, c4 = (i % 10) * 4;
            *(float4*)&sl[e+1][row][c4] = *(const float4*)(base + (size_t)row*NQ + c4);
        }
    }
    __syncthreads();

    const float* __restrict__ ninv = g_ninv + bs*NQ;
    const bool em = (qh > 0)    && (ph > 0);
    const bool ez = true;
    const bool ep = (qh < HS-1) && (ph < HS-1);
    for (int i = tid; i < 1600; i += 256) {
        int qw = i / 40, pw = i % 40;
        bool dp = (qw < HS-1) && (pw < HS-1);
        bool dmm = (qw > 0) && (pw > 0);
        float acc = 0.f;
        #pragma unroll
        for (int eh = 0; eh < 3; ++eh) {
            bool ok = (eh == 0) ? em : ((eh == 1) ? ez : ep);
            if (!ok) continue;
            float s = sl[eh][qw][pw];
            if (dmm) s += sl[eh][qw-1][pw-1];
            if (dp)  s += sl[eh][qw+1][pw+1];
            acc += s;
        }
        Out[(size_t)(qh*HS + qw)*NQ + ph*HS + pw] = acc * ninv[qh*HS + qw];
    }
}

// ---------- pass C (fuse1, flat diag), DIAGONAL MARCHING: bufB -> bufA
__global__ void k_passC() {
    int idx = blockIdx.x*blockDim.x + threadIdx.x;
    const int NP = NQ + 4;                 // p0 in [-3, NQ]
    const int total = NB*2*(NQ/4)*NP;
    if (idx >= total) return;
    int p0 = (idx % NP) - 3;
    int t = idx / NP;
    int qg = t % (NQ/4);
    int bs = t / (NQ/4);
    int q0 = qg * 4;
    const float* __restrict__ S = g_bufB + (size_t)bs*NQ*NQ;
    float* __restrict__ O = g_bufA + (size_t)bs*NQ*NQ;
    float diag[6];
    #pragma unroll
    for (int j = 0; j < 6; ++j) {
        int r = q0 - 1 + j, c = p0 - 1 + j;
        diag[j] = (r >= 0 && r < NQ && c >= 0 && c < NQ) ? S[(size_t)r*NQ + c] : 0.f;
    }
    #pragma unroll
    for (int i = 0; i < 4; ++i) {
        int q = q0 + i, p = p0 + i;
        if (p < 0 || p >= NQ) continue;
        float acc = diag[i+1];
        if (q > 0 && p > 0)       acc += diag[i];
        if (q < NQ-1 && p < NQ-1) acc += diag[i+2];
        O[(size_t)q*NQ + p] = acc;
    }
}

// ---------- pass D (fuse2), DIAGONAL MARCHING in (qh,ph): bufA -> bufB
__global__ void k_passD() {
    int idx = blockIdx.x*blockDim.x + threadIdx.x;
    const int NPH = HS + 3;                // ph0 in [-3, 39] -> 43 values
    const int total = NB*2*10*HS*NPH*HS;   // 2,752,000
    if (idx >= total) return;
    int pw = idx % HS; int t = idx / HS;
    int ph0 = (t % NPH) - 3; t /= NPH;
    int qw = t % HS; t /= HS;
    int qhg = t % 10; int bs = t / 10;
    const float* __restrict__ F = g_bufA + (size_t)bs*NQ*NQ;
    float* __restrict__ O = g_bufB + (size_t)bs*NQ*NQ;
    const int qh0 = qhg*4;
    if (qhg >= 1 && qhg <= 8 && ph0 >= 1 && ph0 <= 34) {
        float diag[6];
        #pragma unroll
        for (int j = 0; j < 6; ++j)
            diag[j] = F[(size_t)((qh0-1+j)*HS + qw)*NQ + (ph0-1+j)*HS + pw];
        #pragma unroll
        for (int i = 0; i < 4; ++i)
            O[(size_t)((qh0+i)*HS + qw)*NQ + (ph0+i)*HS + pw] =
                diag[i] + diag[i+1] + diag[i+2];
    } else {
        #pragma unroll
        for (int i = 0; i < 4; ++i) {
            int qh = qh0 + i, ph = ph0 + i;
            if (ph < 0 || ph >= HS) continue;
            int q = qh*HS + qw, p = ph*HS + pw;
            float acc = F[(size_t)q*NQ + p];
            if (q > 0 && p > 0) {
                int qm = (qh > 0) ? (q - HS) : ((HS-1)*HS + qw - 1);
                int pm = (ph > 0) ? (p - HS) : ((HS-1)*HS + pw - 1);
                acc += F[(size_t)qm*NQ + pm];
            }
            if (q < NQ-1 && p < NQ-1) {
                int qp = (qh < HS-1) ? (q + HS) : (qw + 1);
                int pp = (ph < HS-1) ? (p + HS) : (pw + 1);
                acc += F[(size_t)qp*NQ + pp];
            }
            O[(size_t)q*NQ + p] = acc;
        }
    }
}

// --------------- softmax stats, ONLINE single sweep (reads bufB)
__global__ void k_softmax_stats() {
    int bs = blockIdx.y;
    int p0 = blockIdx.x * 64;
    const float* __restrict__ F = g_bufB + (size_t)bs*NQ*NQ;
    int px = threadIdx.x & 63;
    int qy = threadIdx.x >> 6;        // 0..3
    int p = p0 + px;
    __shared__ float redm[4][64], reds[4][64];
    float mx = -3.4e38f, sm = 0.f;
    for (int q = qy; q < NQ; q += 4) {
        float v = F[(size_t)q*NQ + p];
        if (v <= mx) {
            sm += __expf(SCL * (v - mx));
        } else {
            sm = sm * __expf(SCL * (mx - v)) + 1.f;
            mx = v;
        }
    }
    redm[qy][px] = mx;
    reds[qy][px] = sm;
    __syncthreads();
    if (qy == 0) {
        float m0_ = redm[0][px], m1 = redm[1][px], m2 = redm[2][px], m3 = redm[3][px];
        float M = fmaxf(fmaxf(m0_, m1), fmaxf(m2, m3));
        float S = reds[0][px] * __expf(SCL * (m0_ - M))
                + reds[1][px] * __expf(SCL * (m1 - M))
                + reds[2][px] * __expf(SCL * (m2 - M))
                + reds[3][px] * __expf(SCL * (m3 - M));
        g_smax[bs*NQ + p] = M;
        g_sinv[bs*NQ + p] = 1.0f / S;
    }
}

// --------------- attnT: transposed, normalized attn as half (bufB -> g_ATh)
__global__ void k_attnT() {
    __shared__ float tile[32][33];
    int bs = blockIdx.z;
    int q0 = blockIdx.x * 32, p0 = blockIdx.y * 32;
    const float* __restrict__ F = g_bufB + (size_t)bs*NQ*NQ;
    __half* __restrict__ O = g_ATh + (size_t)bs*NQ*NQ;
    int tx = threadIdx.x, ty = threadIdx.y;  // 32 x 8
    for (int r = ty; r < 32; r += 8)
        tile[r][tx] = F[(size_t)(q0+r)*NQ + p0 + tx];
    __syncthreads();
    for (int r = ty; r < 32; r += 8) {
        int p = p0 + r;
        float e = __expf(SCL * (tile[tx][r] - g_smax[bs*NQ + p])) * g_sinv[bs*NQ + p];
        O[(size_t)p*NQ + q0 + tx] = __float2half_rn(e);
    }
}

// --------------- build paste operand G[bs][m][q] as half, 8 q per thread
__global__ void k_buildG(const float* __restrict__ raw_left,
                         const float* __restrict__ raw_right) {
    int idx = blockIdx.x*blockDim.x + threadIdx.x;
    const int total8 = NB*2*MROWS*(NQ/8);
    if (idx >= total8) return;
    int q8 = (idx % (NQ/8)) * 8;
    int t = idx / (NQ/8);
    int m = t % MROWS;
    int bs = t / MROWS;
    int b = bs >> 1, s = bs & 1;
    int c = m >> 4;
    int o = m & 15;
    int dy = (o >> 2) - 1, dx = (o & 3) - 1;
    int qh = q8 / HS, qw0 = q8 - (q8/HS)*HS;
    int y = 2*qh + dy;
    const float* raw = (s ? raw_right : raw_left) + (size_t)(b*NC + c)*FH*FW;
    __half hv[8];
    if (y >= 0 && y < FH) {
        const float* rrow = raw + (size_t)y*FW;
        #pragma unroll
        for (int j = 0; j < 8; ++j) {
            int x = 2*(qw0 + j) + dx;
            hv[j] = (x >= 0 && x < FW) ? __float2half_rn(rrow[x]) : __half(0.f);
        }
    } else {
        #pragma unroll
        for (int j = 0; j < 8; ++j) hv[j] = __half(0.f);
    }
    *(uint4*)&g_Gh[(size_t)(bs*MROWS + m)*NQ + q8] = *(uint4*)hv;
}

// ------------- GEMM2 (mma.sync fp16, f32 accum): T[m,p] = sum_q G[m,q] * attnT[p,q]
// CTA tile 256(m) x 128(n), 512 threads (16 warps: 4m x 4n), warp tile 64x32.
__global__ void __launch_bounds__(512) k_gemm2h() {
    extern __shared__ char smx[];
    const int bs = blockIdx.z;
    const __half* __restrict__ Gm = g_Gh  + (size_t)bs*MROWS*NQ;
    const __half* __restrict__ Bm = g_ATh + (size_t)bs*NQ*NQ;
    float* __restrict__ Tm = g_T + (size_t)bs*MROWS*NQ;
    const int m0 = blockIdx.x * 256, n0 = blockIdx.y * 128;
    const int t = threadIdx.x;
    const int lane = t & 31, wid = t >> 5;
    const int wm = wid & 3, wn = wid >> 2;      // warp grid 4(m) x 4(n)

    const int aRow = t >> 1, psA = t & 1;
    const int aMg = aRow >> 4, aRr = aRow & 15;
    const int aPg = aRr & 7;
    const int aHw = (aRr >> 3) << 3;
    const bool hasB = (t < 256);
    const int bRow = t >> 1;
    const int psB = t & 1;
    const int bNg = bRow >> 3, bPg = bRow & 7;
    const bool pBvalid = hasB && ((n0 + bRow) < NQ);

    uint32_t al[4], ah[4], bl[4], bh[4];

    float acc[4][4][4];
    #pragma unroll
    for (int i=0;i<4;i++)
        #pragma unroll
        for (int j=0;j<4;j++)
            #pragma unroll
            for (int k=0;k<4;k++) acc[i][j][k] = 0.f;

    {
        const uint4* pa = (const uint4*)(Gm + (size_t)(m0+aRow)*NQ + psA*16);
        uint4 lo = pa[0], hi = pa[1];
        al[0]=lo.x; al[1]=lo.y; al[2]=lo.z; al[3]=lo.w;
        ah[0]=hi.x; ah[1]=hi.y; ah[2]=hi.z; ah[3]=hi.w;
        if (pBvalid) {
            const uint4* pb = (const uint4*)(Bm + (size_t)(n0+bRow)*NQ + psB*16);
            uint4 blo = pb[0], bhi = pb[1];
            bl[0]=blo.x; bl[1]=blo.y; bl[2]=blo.z; bl[3]=blo.w;
            bh[0]=bhi.x; bh[1]=bhi.y; bh[2]=bhi.z; bh[3]=bhi.w;
        } else {
            #pragma unroll
            for (int j=0;j<4;j++) { bl[j]=0u; bh[j]=0u; }
        }
    }

    const int NTILES = NQ / KT;
    for (int it = 0; it < NTILES; ++it) {
        char* base = smx + (it & 1) * 24576;
        char* Asl = base;
        char* Bsl = base + 16384;

        {
            char* aw = Asl + ((psA*16 + aMg)*32 + aPg*4) * 16 + aHw;
            #pragma unroll
            for (int j = 0; j < 4; ++j)
                *(uint2*)(aw + j*16) = make_uint2(al[j], ah[j]);
            if (hasB) {
                char* bw = Bsl + ((psB*16 + bNg)*32 + bPg*4) * 8;
                #pragma unroll
                for (int j = 0; j < 4; ++j)
                    *(uint2*)(bw + j*8)  = make_uint2(bl[j], bh[j]);
            }
        }
        __syncthreads();

        if (it + 1 < NTILES) {
            int k0n = (it + 1) * KT;
            const uint4* pa = (const uint4*)(Gm + (size_t)(m0+aRow)*NQ + k0n + psA*16);
            uint4 lo = pa[0], hi = pa[1];
            al[0]=lo.x; al[1]=lo.y; al[2]=lo.z; al[3]=lo.w;
            ah[0]=hi.x; ah[1]=hi.y; ah[2]=hi.z; ah[3]=hi.w;
            if (pBvalid) {
                const uint4* pb = (const uint4*)(Bm + (size_t)(n0+bRow)*NQ + k0n + psB*16);
                uint4 blo = pb[0], bhi = pb[1];
                bl[0]=blo.x; bl[1]=blo.y; bl[2]=blo.z; bl[3]=blo.w;
                bh[0]=bhi.x; bh[1]=bhi.y; bh[2]=bhi.z; bh[3]=bhi.w;
            }
        }

        #pragma unroll
        for (int s = 0; s < 2; ++s) {
            uint4 af[4]; uint2 bf[4];
            #pragma unroll
            for (int mt = 0; mt < 4; ++mt)
                af[mt] = *(const uint4*)(Asl + (((s*16 + wm*4 + mt)*32 + lane) * 16));
            #pragma unroll
            for (int nt = 0; nt < 4; ++nt)
                bf[nt] = *(const uint2*)(Bsl + (((s*16 + wn*4 + nt)*32 + lane) * 8));
            #pragma unroll
            for (int mt = 0; mt < 4; ++mt)
                #pragma unroll
                for (int nt = 0; nt < 4; ++nt)
                    mma_f16(acc[mt][nt], af[mt].x, af[mt].z, af[mt].y, af[mt].w,
                            bf[nt].x, bf[nt].y);
        }
    }

    #pragma unroll
    for (int mt = 0; mt < 4; ++mt) {
        int m = m0 + wm*64 + mt*16 + (lane >> 2);
        #pragma unroll
        for (int nt = 0; nt < 4; ++nt) {
            int n = n0 + wn*32 + nt*8 + 2*(lane & 3);
            if (n < NQ) {
                *(float2*)&Tm[(size_t)m*NQ + n]     = make_float2(acc[mt][nt][0], acc[mt][nt][1]);
                *(float2*)&Tm[(size_t)(m+8)*NQ + n] = make_float2(acc[mt][nt][2], acc[mt][nt][3]);
            }
        }
    }
}

// ------------- gather epilogue + cosine-window blend -> output (2,128,80,80)
__global__ void k_combine(float* __restrict__ out) {
    int idx = blockIdx.x*blockDim.x + threadIdx.x;
    const int total = NB*NC*FH*FW;
    if (idx >= total) return;
    int X = idx % FW; int t = idx / FW;
    int Y = t % FH; t /= FH;
    int c = t % NC; int b = t / NC;

    int dys[2], hh[2]; int ny = 0;
    if ((Y & 1) == 0) {
        dys[ny] = 0; hh[ny] = Y >> 1; ny++;
        if (Y >= 2) { dys[ny] = 2; hh[ny] = (Y-2) >> 1; ny++; }
    } else {
        dys[ny] = 1; hh[ny] = (Y-1) >> 1; ny++;
        if (Y <= 2*HS - 3) { dys[ny] = -1; hh[ny] = (Y+1) >> 1; ny++; }
    }
    int dxs[2], ww[2]; int nx = 0;
    if ((X & 1) == 0) {
        dxs[nx] = 0; ww[nx] = X >> 1; nx++;
        if (X >= 2) { dxs[nx] = 2; ww[nx] = (X-2) >> 1; nx++; }
    } else {
        dxs[nx] = 1; ww[nx] = (X-1) >> 1; nx++;
        if (X <= 2*HS - 3) { dxs[nx] = -1; ww[nx] = (X+1) >> 1; nx++; }
    }

    const float PI = 3.14159265358979323846f;
    float wl = 0.5f*(1.f + cosf(PI * (float)X        / (float)(FW-1)));
    float wr = 0.5f*(1.f + cosf(PI * (float)(FW-1-X) / (float)(FW-1)));

    float res = 0.f;
    for (int s = 0; s < 2; ++s) {
        const float* T = g_T + (size_t)(b*2 + s)*MROWS*NQ;
        float acc = 0.f;
        for (int iy = 0; iy < ny; ++iy) {
            for (int ix = 0; ix < nx; ++ix) {
                int m = c*16 + (dys[iy]+1)*4 + (dxs[ix]+1);
                acc += T[(size_t)m*NQ + hh[iy]*HS + ww[ix]];
            }
        }
        res += (s == 0 ? wl : wr) * 0.25f * acc;
    }
    out[idx] = res;
}

// ------------------------------------------------------------------ launcher
extern "C" void kernel_launch(void* const* d_in, const int* in_sizes, int n_in,
                              void* d_out, int out_size) {
    const float* left      = (const float*)d_in[0];
    const float* right     = (const float*)d_in[1];
    const float* mid       = (const float*)d_in[2];
    const float* raw_left  = (const float*)d_in[3];
    const float* raw_right = (const float*)d_in[4];
    float* outp = (float*)d_out;

    cudaFuncSetAttribute(k_gemm2h, cudaFuncAttributeMaxDynamicSharedMemorySize, G2_SMEM);

    k_cvt<<<dim3(NQ/32, NC/32, NB*3), dim3(32, 8)>>>(left, right, mid);
    int t2 = NB*2*NQ;
    k_sumsq<<<(t2+127)/128, 128>>>();
    k_norm<<<(t2+127)/128, 128>>>();

    dim3 g1((NQ+127)/128, (NQ+127)/128, NB*2);   // 13 x 13 x 4
    k_gemm1h<<<g1, 256>>>();

    k_psAB<<<NB*2*HS*HS, 256>>>();               // fused passes A+B

    int tC = NB*2*(NQ/4)*(NQ+4);
    k_passC<<<(tC+255)/256, 256>>>();

    int tD = NB*2*10*HS*(HS+3)*HS;
    k_passD<<<(tD+255)/256, 256>>>();

    k_softmax_stats<<<dim3(NQ/64, NB*2), 256>>>();
    k_attnT<<<dim3(NQ/32, NQ/32, NB*2), dim3(32, 8)>>>();

    int tg8 = NB*2*MROWS*(NQ/8);
    k_buildG<<<(tg8+255)/256, 256>>>(raw_left, raw_right);

    dim3 g2(MROWS/256, (NQ+127)/128, NB*2);      // 8 x 13 x 4
    k_gemm2h<<<g2, 512, G2_SMEM>>>();

    int to = NB*NC*FH*FW;
    k_combine<<<(to+255)/256, 256>>>(outp);
}